// round 1
// baseline (speedup 1.0000x reference)
#include <cuda_runtime.h>
#include <cstdint>

// ---------------------------------------------------------------------------
// BERTHeading: 3 token-window convs (GEMMs) + positional max + L2 norms +
// pooled vector + sentence projection.
//
// Decomposition:
//   conv-k output row (s,t) = relu( dot(x[s, t:t+k] (768k contig floats), Wk_flat) + bk )
//   -> plain GEMM with overlapping A rows, K_eff = 768*k, N = 512.
// Scratch for a/b/c in __device__ globals (no allocations).
// ---------------------------------------------------------------------------

#define BS      4096
#define SEQ     20
#define EMB     768
#define FEAT    512

__device__ float g_A[BS * 20 * FEAT];   // conv1 out  [4096*20, 512]
__device__ float g_B[BS * 19 * FEAT];   // conv2 out  [4096*19, 512]
__device__ float g_C[BS * 18 * FEAT];   // conv3 out  [4096*18, 512]

// ---- packed f32x2 helpers (sm_100+; ptxas never auto-fuses these) ----------
__device__ __forceinline__ unsigned long long pack2(float lo, float hi) {
    unsigned long long r;
    asm("mov.b64 %0, {%1, %2};" : "=l"(r) : "f"(lo), "f"(hi));
    return r;
}
__device__ __forceinline__ void unpack2(unsigned long long v, float& lo, float& hi) {
    asm("mov.b64 {%0, %1}, %2;" : "=f"(lo), "=f"(hi) : "l"(v));
}
__device__ __forceinline__ void fma2(unsigned long long& d,
                                     unsigned long long a, unsigned long long b) {
    asm("fma.rn.f32x2 %0, %1, %2, %0;" : "+l"(d) : "l"(a), "l"(b));
}

// ---------------------------------------------------------------------------
// Fused GEMM: Y[m, n] = act( sum_k A(m,k) * W[k*512+n] + bias[n] )
//   A(m, :) = X + (m/T)*sampleStride + (m%T)*768   (contiguous K_eff floats)
// Tile: BM=128, BN=128, BK=8, 256 threads, 8x8 outputs/thread (as 8x4 f32x2).
// Grid: (M/128, 512/128). All dims divide exactly for this problem.
// sel: 0 -> g_A, 1 -> g_B, 2 -> g_C, 3 -> Yext
// ---------------------------------------------------------------------------
__global__ void __launch_bounds__(256, 2)
sgemm_fused(const float* __restrict__ X, const float* __restrict__ W,
            const float* __restrict__ bias, float* __restrict__ Yext,
            int sel, int M, int K, int T, int sampleStride, int doRelu)
{
    float* Y = (sel == 0) ? g_A : (sel == 1) ? g_B : (sel == 2) ? g_C : Yext;

    __shared__ float As[8][132];   // [BK][BM+4] transposed, padded
    __shared__ float Bs[8][128];   // [BK][BN]

    const int tid = threadIdx.x;
    const int tx  = tid & 15;      // 0..15  -> n sub-tile
    const int ty  = tid >> 4;      // 0..15  -> m sub-tile

    // A tile loader: each thread one float4 (row = tid/2, col = (tid&1)*4)
    const int arow = tid >> 1;
    const int acol = (tid & 1) * 4;
    const int m_load = blockIdx.x * 128 + arow;
    const size_t abase = (size_t)(m_load / T) * (size_t)sampleStride
                       + (size_t)(m_load % T) * 768 + acol;

    // B tile loader: each thread one float4 (row = tid/32, col = (tid&31)*4)
    const int brow = tid >> 5;
    const int bcol = (tid & 31) * 4;
    const float* Wp = W + (size_t)brow * FEAT + (size_t)blockIdx.y * 128 + bcol;

    unsigned long long acc[8][4];
    #pragma unroll
    for (int i = 0; i < 8; i++)
        #pragma unroll
        for (int j = 0; j < 4; j++) acc[i][j] = 0ull;

    for (int k0 = 0; k0 < K; k0 += 8) {
        float4 a4 = *(const float4*)(X + abase + k0);
        float4 b4 = *(const float4*)(Wp + (size_t)k0 * FEAT);
        As[acol + 0][arow] = a4.x;
        As[acol + 1][arow] = a4.y;
        As[acol + 2][arow] = a4.z;
        As[acol + 3][arow] = a4.w;
        *(float4*)&Bs[brow][bcol] = b4;
        __syncthreads();

        #pragma unroll
        for (int kk = 0; kk < 8; kk++) {
            float4 am0 = *(const float4*)&As[kk][ty * 8];
            float4 am1 = *(const float4*)&As[kk][ty * 8 + 4];
            unsigned long long bn[4];
            bn[0] = *(const unsigned long long*)&Bs[kk][tx * 8 + 0];
            bn[1] = *(const unsigned long long*)&Bs[kk][tx * 8 + 2];
            bn[2] = *(const unsigned long long*)&Bs[kk][tx * 8 + 4];
            bn[3] = *(const unsigned long long*)&Bs[kk][tx * 8 + 6];

            unsigned long long ap;
            ap = pack2(am0.x, am0.x);
            #pragma unroll
            for (int j = 0; j < 4; j++) fma2(acc[0][j], ap, bn[j]);
            ap = pack2(am0.y, am0.y);
            #pragma unroll
            for (int j = 0; j < 4; j++) fma2(acc[1][j], ap, bn[j]);
            ap = pack2(am0.z, am0.z);
            #pragma unroll
            for (int j = 0; j < 4; j++) fma2(acc[2][j], ap, bn[j]);
            ap = pack2(am0.w, am0.w);
            #pragma unroll
            for (int j = 0; j < 4; j++) fma2(acc[3][j], ap, bn[j]);
            ap = pack2(am1.x, am1.x);
            #pragma unroll
            for (int j = 0; j < 4; j++) fma2(acc[4][j], ap, bn[j]);
            ap = pack2(am1.y, am1.y);
            #pragma unroll
            for (int j = 0; j < 4; j++) fma2(acc[5][j], ap, bn[j]);
            ap = pack2(am1.z, am1.z);
            #pragma unroll
            for (int j = 0; j < 4; j++) fma2(acc[6][j], ap, bn[j]);
            ap = pack2(am1.w, am1.w);
            #pragma unroll
            for (int j = 0; j < 4; j++) fma2(acc[7][j], ap, bn[j]);
        }
        __syncthreads();
    }

    // Epilogue: bias (+ optional relu), write Y[m*512 + n]
    const int mbase = blockIdx.x * 128 + ty * 8;
    const int nbase = blockIdx.y * 128 + tx * 8;
    float bb[8];
    #pragma unroll
    for (int j = 0; j < 8; j++) bb[j] = bias[nbase + j];

    #pragma unroll
    for (int i = 0; i < 8; i++) {
        float o[8];
        #pragma unroll
        for (int j = 0; j < 4; j++) {
            float lo, hi;
            unpack2(acc[i][j], lo, hi);
            o[2 * j + 0] = lo;
            o[2 * j + 1] = hi;
        }
        #pragma unroll
        for (int j = 0; j < 8; j++) {
            float v = o[j] + bb[j];
            o[j] = doRelu ? fmaxf(v, 0.0f) : v;
        }
        float* yr = Y + (size_t)(mbase + i) * FEAT + nbase;
        *(float4*)(yr + 0) = make_float4(o[0], o[1], o[2], o[3]);
        *(float4*)(yr + 4) = make_float4(o[4], o[5], o[6], o[7]);
    }
}

// ---------------------------------------------------------------------------
// Epilogue: per sample s (block), 512 threads (one per feature c).
//   code[t] = max(a[t], b_pad[t], c_pad[t]); L2-normalize over c per t;
//   words_out[s][c][t] = code/norm  (transposed write, 20 contiguous floats/c)
//   pooled = (max_t a + max_t b + max_t c)/3; word_vec = pooled / ||pooled||
// ---------------------------------------------------------------------------
__global__ void __launch_bounds__(512)
epilogue_kernel(float* __restrict__ words_out, float* __restrict__ word_vec)
{
    const int s = blockIdx.x;
    const int c = threadIdx.x;
    const int lane = c & 31;
    const int wid  = c >> 5;   // 0..15

    __shared__ float red[21][16];
    __shared__ float invn[21];

    const float* Ab = g_A + (size_t)s * 20 * FEAT + c;
    const float* Bb = g_B + (size_t)s * 19 * FEAT + c;
    const float* Cb = g_C + (size_t)s * 18 * FEAT + c;

    float code[20];
    float ma = 0.0f, mb = 0.0f, mc = 0.0f;

    #pragma unroll
    for (int t = 0; t < 20; t++) {
        float av = Ab[t * FEAT];
        float bv = (t < 19) ? Bb[t * FEAT] : 0.0f;   // relu outputs >= 0: pad-0 ok
        float cv = (t < 18) ? Cb[t * FEAT] : 0.0f;
        ma = fmaxf(ma, av);
        mb = fmaxf(mb, bv);
        mc = fmaxf(mc, cv);
        float cd = fmaxf(av, fmaxf(bv, cv));
        code[t] = cd;
        float ss = cd * cd;
        #pragma unroll
        for (int o = 16; o > 0; o >>= 1) ss += __shfl_xor_sync(0xffffffffu, ss, o);
        if (lane == 0) red[t][wid] = ss;
    }

    float pooled = (ma + mb + mc) * (1.0f / 3.0f);
    {
        float ps = pooled * pooled;
        #pragma unroll
        for (int o = 16; o > 0; o >>= 1) ps += __shfl_xor_sync(0xffffffffu, ps, o);
        if (lane == 0) red[20][wid] = ps;
    }
    __syncthreads();

    if (c < 21) {
        float ssum = 0.0f;
        #pragma unroll
        for (int i = 0; i < 16; i++) ssum += red[c][i];
        invn[c] = 1.0f / fmaxf(sqrtf(ssum), 1e-12f);
    }
    __syncthreads();

    // words_out[s][c][0..19]: 20 contiguous floats, 16B aligned (c*80 bytes)
    float* op = words_out + (size_t)s * FEAT * 20 + (size_t)c * 20;
    #pragma unroll
    for (int q = 0; q < 5; q++) {
        float4 v;
        v.x = code[q * 4 + 0] * invn[q * 4 + 0];
        v.y = code[q * 4 + 1] * invn[q * 4 + 1];
        v.z = code[q * 4 + 2] * invn[q * 4 + 2];
        v.w = code[q * 4 + 3] * invn[q * 4 + 3];
        *(float4*)(op + q * 4) = v;
    }

    word_vec[(size_t)s * FEAT + c] = pooled * invn[20];
}

// ---------------------------------------------------------------------------
// Launch. Inputs (metadata order):
//  0 words_emb [4096,20,768]  1 sent_emb [4096,768]
//  2 W1 [1,768,512]  3 b1 [512]  4 W2 [2,768,512]  5 b2 [512]
//  6 W3 [3,768,512]  7 b3 [512]  8 Wp [768,512]    9 bp [512]
// Output (flattened tuple): words_out [4096,512,20] | word_vector [4096,512]
//                           | sent [4096,512]
// ---------------------------------------------------------------------------
extern "C" void kernel_launch(void* const* d_in, const int* in_sizes, int n_in,
                              void* d_out, int out_size)
{
    const float* words = (const float*)d_in[0];
    const float* sentE = (const float*)d_in[1];
    const float* W1 = (const float*)d_in[2];
    const float* b1 = (const float*)d_in[3];
    const float* W2 = (const float*)d_in[4];
    const float* b2 = (const float*)d_in[5];
    const float* W3 = (const float*)d_in[6];
    const float* b3 = (const float*)d_in[7];
    const float* Wp = (const float*)d_in[8];
    const float* bp = (const float*)d_in[9];

    float* out       = (float*)d_out;
    float* words_out = out;                                  // 41,943,040
    float* word_vec  = out + (size_t)BS * FEAT * 20;         // +2,097,152
    float* sent_out  = word_vec + (size_t)BS * FEAT;         // +2,097,152

    const int SSTRIDE = SEQ * EMB;  // 15360

    // conv1: M=81920, K=768
    sgemm_fused<<<dim3(640, 4), 256>>>(words, W1, b1, nullptr, 0,
                                       BS * 20, 768, 20, SSTRIDE, 1);
    // conv2: M=77824, K=1536
    sgemm_fused<<<dim3(608, 4), 256>>>(words, W2, b2, nullptr, 1,
                                       BS * 19, 1536, 19, SSTRIDE, 1);
    // conv3: M=73728, K=2304
    sgemm_fused<<<dim3(576, 4), 256>>>(words, W3, b3, nullptr, 2,
                                       BS * 18, 2304, 18, SSTRIDE, 1);
    // sentence projection: M=4096, K=768, no relu, straight to output
    sgemm_fused<<<dim3(32, 4), 256>>>(sentE, Wp, bp, sent_out, 3,
                                      BS, 768, 1, EMB, 0);
    // fused max / norms / transpose / pooling
    epilogue_kernel<<<BS, 512>>>(words_out, word_vec);
}

// round 3
// speedup vs baseline: 2.4529x; 2.4529x over previous
#include <cuda_runtime.h>
#include <cstdint>

// ---------------------------------------------------------------------------
// BERTHeading via warp-level mma.sync tf32 GEMMs (tcgen05 unavailable: the
// harness lowers through compute_103 PTX, which rejects sm_103a features).
//
//   conv-k row (s,t) = relu( dot(words[s, t:t+k] (contig 768k f32), Wk) + bk )
//   -> GEMM, K_eff = 768k, N = 512.
// Tile: BM=128 x BN=256, K-chunk 32 f32. 8 warps, 64x64 warp tile.
// SMEM pad-36 layout -> conflict-free fragment LDS. 2-stage cp.async pipeline.
// ---------------------------------------------------------------------------

#define BS      4096
#define EMB     768
#define FEAT    512

#define BM      128
#define BN      256
#define BKF     32
#define KPAD    36
#define ASZ     (BM * KPAD)          // 4608 floats
#define BSZ     (BN * KPAD)          // 9216 floats
#define STG     (ASZ + BSZ)          // 13824 floats / stage
#define SMEM_TOTAL (2 * STG * 4)     // 110592 bytes

__device__ float g_A[BS * 20 * FEAT];
__device__ float g_B[BS * 19 * FEAT];
__device__ float g_C[BS * 18 * FEAT];
// transposed + tf32-rounded weights, [512, K] row-major: W1 | W2 | W3 | Wp
__device__ float g_Wt[512 * (768 + 1536 + 2304 + 768)];

#define CP_ASYNC16(saddr, gptr) \
    asm volatile("cp.async.cg.shared.global [%0], [%1], 16;" :: "r"(saddr), "l"(gptr))
#define CP_COMMIT() asm volatile("cp.async.commit_group;" ::: "memory")
#define CP_WAIT1()  asm volatile("cp.async.wait_group 1;" ::: "memory")

__device__ __forceinline__ uint32_t smem_u32(const void* p) {
    uint32_t a;
    asm("{ .reg .u64 t; cvta.to.shared.u64 t, %1; cvt.u32.u64 %0, t; }"
        : "=r"(a) : "l"(p));
    return a;
}

__device__ __forceinline__ void mma_tf32(float* d, const uint32_t* a,
                                         const uint32_t* b) {
    asm volatile(
        "mma.sync.aligned.m16n8k8.row.col.f32.tf32.tf32.f32 "
        "{%0,%1,%2,%3}, {%4,%5,%6,%7}, {%8,%9}, {%0,%1,%2,%3};"
        : "+f"(d[0]), "+f"(d[1]), "+f"(d[2]), "+f"(d[3])
        : "r"(a[0]), "r"(a[1]), "r"(a[2]), "r"(a[3]), "r"(b[0]), "r"(b[1]));
}

// ---------------------------------------------------------------------------
// Weight transpose + tf32 rounding: W [K,512] -> Wt [512,K] (rna-rounded)
// ---------------------------------------------------------------------------
__global__ void transpose_w(const float* __restrict__ W, float* __restrict__ Wt,
                            int K)
{
    __shared__ float t[32][33];
    const int kb = blockIdx.x * 32, nb = blockIdx.y * 32;
    const int x = threadIdx.x, y = threadIdx.y;   // 32 x 8
    #pragma unroll
    for (int i = 0; i < 32; i += 8)
        t[y + i][x] = W[(size_t)(kb + y + i) * FEAT + nb + x];
    __syncthreads();
    #pragma unroll
    for (int i = 0; i < 32; i += 8) {
        float v = t[x][y + i];
        uint32_t u;
        asm("cvt.rna.tf32.f32 %0, %1;" : "=r"(u) : "f"(v));
        Wt[(size_t)(nb + y + i) * K + kb + x] = __uint_as_float(u);
    }
}

// ---------------------------------------------------------------------------
// tf32 mma.sync GEMM.
//   Y[m, nb..nb+255] = act( A(m,:) @ Wt[nb..nb+255,:]^T + bias )
//   A(m,:) = X + (m/T)*srcStride + (m%T)*768, contiguous K floats.
// Grid: (M/128, 512/256). 256 threads.
// ---------------------------------------------------------------------------
__global__ void __launch_bounds__(256, 1)
gemm_mma(const float* __restrict__ X, const float* __restrict__ Wt,
         const float* __restrict__ bias, float* __restrict__ Yext,
         int sel, int K, int T, int srcStride, int doRelu)
{
    extern __shared__ float smem[];
    float* Y = (sel == 0) ? g_A : (sel == 1) ? g_B : (sel == 2) ? g_C : Yext;

    const int tid  = threadIdx.x;
    const int lane = tid & 31;
    const int wid  = tid >> 5;
    const int wm   = wid & 1;        // 2 m-warps
    const int wn   = wid >> 1;       // 4 n-warps
    const int r    = lane >> 2;      // 0..7
    const int cq   = lane & 3;       // 0..3

    const int nb = blockIdx.y * BN;

    // ---- loader addresses ----
    // A: row = tid/2 (128 rows), 4 x 16B at koff = (tid&1)*16
    const int am   = blockIdx.x * BM + (tid >> 1);
    const int akof = (tid & 1) * 16;
    const float* aRow = X + (size_t)(am / T) * srcStride
                          + (size_t)(am % T) * EMB + akof;
    const uint32_t aDst = smem_u32(smem) + ((tid >> 1) * KPAD + akof) * 4;
    // B: row = tid (256 rows), 8 x 16B
    const float* bRow = Wt + (size_t)(nb + tid) * K;
    const uint32_t bDst = smem_u32(smem) + (ASZ + tid * KPAD) * 4;

    const int Kc = K / BKF;

    auto load_chunk = [&](int chunk) {
        const uint32_t so = (uint32_t)((chunk & 1) * STG * 4);
        const int kc = chunk * BKF;
        #pragma unroll
        for (int j = 0; j < 4; j++)
            CP_ASYNC16(aDst + so + j * 16, aRow + kc + j * 4);
        #pragma unroll
        for (int j = 0; j < 8; j++)
            CP_ASYNC16(bDst + so + j * 16, bRow + kc + j * 4);
    };

    float acc[4][8][4];
    #pragma unroll
    for (int mi = 0; mi < 4; mi++)
        #pragma unroll
        for (int nj = 0; nj < 8; nj++)
            #pragma unroll
            for (int q = 0; q < 4; q++) acc[mi][nj][q] = 0.0f;

    load_chunk(0);
    CP_COMMIT();

    // compute-fragment smem base offsets (floats)
    const int aBaseRow = wm * 64 + r;          // + mi*16 (+8)
    const int bBaseRow = wn * 64 + r;          // + nj*8

    for (int c = 0; c < Kc; c++) {
        __syncthreads();          // all warps done reading stage (c+1)&1
        if (c + 1 < Kc) load_chunk(c + 1);
        CP_COMMIT();
        CP_WAIT1();               // chunk c resident
        __syncthreads();

        const float* As = smem + (c & 1) * STG;
        const float* Bs = As + ASZ;

        #pragma unroll
        for (int ks = 0; ks < 4; ks++) {
            const int kb0 = ks * 8 + cq;
            uint32_t af[4][4];
            #pragma unroll
            for (int mi = 0; mi < 4; mi++) {
                const int row0 = aBaseRow + mi * 16;
                af[mi][0] = __float_as_uint(As[row0 * KPAD + kb0]);
                af[mi][1] = __float_as_uint(As[(row0 + 8) * KPAD + kb0]);
                af[mi][2] = __float_as_uint(As[row0 * KPAD + kb0 + 4]);
                af[mi][3] = __float_as_uint(As[(row0 + 8) * KPAD + kb0 + 4]);
            }
            uint32_t bf[8][2];
            #pragma unroll
            for (int nj = 0; nj < 8; nj++) {
                const int nrow = bBaseRow + nj * 8;
                bf[nj][0] = __float_as_uint(Bs[nrow * KPAD + kb0]);
                bf[nj][1] = __float_as_uint(Bs[nrow * KPAD + kb0 + 4]);
            }
            #pragma unroll
            for (int mi = 0; mi < 4; mi++)
                #pragma unroll
                for (int nj = 0; nj < 8; nj++)
                    mma_tf32(acc[mi][nj], af[mi], bf[nj]);
        }
    }

    // ---- epilogue: bias (+relu), write Y ----
    const int mBase = blockIdx.x * BM + wm * 64 + r;
    const int nBase = nb + wn * 64 + cq * 2;
    float bb[8][2];
    #pragma unroll
    for (int nj = 0; nj < 8; nj++) {
        bb[nj][0] = __ldg(bias + nBase + nj * 8);
        bb[nj][1] = __ldg(bias + nBase + nj * 8 + 1);
    }
    #pragma unroll
    for (int mi = 0; mi < 4; mi++) {
        #pragma unroll
        for (int rr = 0; rr < 2; rr++) {
            float* yr = Y + (size_t)(mBase + mi * 16 + rr * 8) * FEAT;
            #pragma unroll
            for (int nj = 0; nj < 8; nj++) {
                float v0 = acc[mi][nj][rr * 2 + 0] + bb[nj][0];
                float v1 = acc[mi][nj][rr * 2 + 1] + bb[nj][1];
                if (doRelu) { v0 = fmaxf(v0, 0.0f); v1 = fmaxf(v1, 0.0f); }
                *(float2*)(yr + nBase + nj * 8) = make_float2(v0, v1);
            }
        }
    }
}

// ---------------------------------------------------------------------------
// Epilogue: positional max of 3 convs, per-token L2 norm, transpose write,
// pooled word vector. One block per sample, 512 threads (one per feature).
// ---------------------------------------------------------------------------
__global__ void __launch_bounds__(512)
epilogue_kernel(float* __restrict__ words_out, float* __restrict__ word_vec)
{
    const int s = blockIdx.x;
    const int c = threadIdx.x;
    const int lane = c & 31;
    const int wid  = c >> 5;

    __shared__ float red[21][16];
    __shared__ float invn[21];

    const float* Ab = g_A + (size_t)s * 20 * FEAT + c;
    const float* Bb = g_B + (size_t)s * 19 * FEAT + c;
    const float* Cb = g_C + (size_t)s * 18 * FEAT + c;

    float code[20];
    float ma = 0.0f, mb = 0.0f, mc = 0.0f;

    #pragma unroll
    for (int t = 0; t < 20; t++) {
        float av = Ab[t * FEAT];
        float bv = (t < 19) ? Bb[t * FEAT] : 0.0f;   // relu >= 0: 0-pad exact
        float cv = (t < 18) ? Cb[t * FEAT] : 0.0f;
        ma = fmaxf(ma, av);
        mb = fmaxf(mb, bv);
        mc = fmaxf(mc, cv);
        float cd = fmaxf(av, fmaxf(bv, cv));
        code[t] = cd;
        float ss = cd * cd;
        #pragma unroll
        for (int o = 16; o > 0; o >>= 1) ss += __shfl_xor_sync(0xffffffffu, ss, o);
        if (lane == 0) red[t][wid] = ss;
    }

    float pooled = (ma + mb + mc) * (1.0f / 3.0f);
    {
        float ps = pooled * pooled;
        #pragma unroll
        for (int o = 16; o > 0; o >>= 1) ps += __shfl_xor_sync(0xffffffffu, ps, o);
        if (lane == 0) red[20][wid] = ps;
    }
    __syncthreads();

    if (c < 21) {
        float ssum = 0.0f;
        #pragma unroll
        for (int i = 0; i < 16; i++) ssum += red[c][i];
        invn[c] = 1.0f / fmaxf(sqrtf(ssum), 1e-12f);
    }
    __syncthreads();

    float* op = words_out + (size_t)s * FEAT * 20 + (size_t)c * 20;
    #pragma unroll
    for (int q = 0; q < 5; q++) {
        float4 v;
        v.x = code[q * 4 + 0] * invn[q * 4 + 0];
        v.y = code[q * 4 + 1] * invn[q * 4 + 1];
        v.z = code[q * 4 + 2] * invn[q * 4 + 2];
        v.w = code[q * 4 + 3] * invn[q * 4 + 3];
        *(float4*)(op + q * 4) = v;
    }
    word_vec[(size_t)s * FEAT + c] = pooled * invn[20];
}

// ---------------------------------------------------------------------------
extern "C" void kernel_launch(void* const* d_in, const int* in_sizes, int n_in,
                              void* d_out, int out_size)
{
    const float* words = (const float*)d_in[0];
    const float* sentE = (const float*)d_in[1];
    const float* W1 = (const float*)d_in[2];
    const float* b1 = (const float*)d_in[3];
    const float* W2 = (const float*)d_in[4];
    const float* b2 = (const float*)d_in[5];
    const float* W3 = (const float*)d_in[6];
    const float* b3 = (const float*)d_in[7];
    const float* Wp = (const float*)d_in[8];
    const float* bp = (const float*)d_in[9];

    float* out       = (float*)d_out;
    float* words_out = out;
    float* word_vec  = out + (size_t)BS * FEAT * 20;
    float* sent_out  = word_vec + (size_t)BS * FEAT;

    cudaFuncSetAttribute(gemm_mma, cudaFuncAttributeMaxDynamicSharedMemorySize,
                         SMEM_TOTAL);

    float* g_wt_base;
    cudaGetSymbolAddress((void**)&g_wt_base, g_Wt);
    float* wt1 = g_wt_base;
    float* wt2 = wt1 + (size_t)512 * 768;
    float* wt3 = wt2 + (size_t)512 * 1536;
    float* wtp = wt3 + (size_t)512 * 2304;

    transpose_w<<<dim3(768 / 32, 16),  dim3(32, 8)>>>(W1, wt1, 768);
    transpose_w<<<dim3(1536 / 32, 16), dim3(32, 8)>>>(W2, wt2, 1536);
    transpose_w<<<dim3(2304 / 32, 16), dim3(32, 8)>>>(W3, wt3, 2304);
    transpose_w<<<dim3(768 / 32, 16),  dim3(32, 8)>>>(Wp, wtp, 768);

    const int SSTRIDE = 20 * EMB;   // 15360

    // conv1: M=81920, K=768
    gemm_mma<<<dim3(640, 2), 256, SMEM_TOTAL>>>(words, wt1, b1, nullptr,
                                                0, 768, 20, SSTRIDE, 1);
    // conv2: M=77824, K=1536
    gemm_mma<<<dim3(608, 2), 256, SMEM_TOTAL>>>(words, wt2, b2, nullptr,
                                                1, 1536, 19, SSTRIDE, 1);
    // conv3: M=73728, K=2304
    gemm_mma<<<dim3(576, 2), 256, SMEM_TOTAL>>>(words, wt3, b3, nullptr,
                                                2, 2304, 18, SSTRIDE, 1);
    // sentence projection: M=4096, K=768
    gemm_mma<<<dim3(32, 2), 256, SMEM_TOTAL>>>(sentE, wtp, bp, sent_out,
                                               3, 768, 1, EMB, 0);

    epilogue_kernel<<<BS, 512>>>(words_out, word_vec);
}